// round 1
// baseline (speedup 1.0000x reference)
#include <cuda_runtime.h>
#include <cuda_bf16.h>
#include <cstdint>

#define BIMG 16
#define AANC 65536
#define GGT  32

// ---------------- device scratch (static, no allocations) ----------------
__device__ unsigned            gNumPos[BIMG];
__device__ double              gLocSum[BIMG];
__device__ double              gPosBce[BIMG];
__device__ double              gNegSum[BIMG];
__device__ unsigned            gPredCnt[BIMG];
__device__ double              gIouSum;
__device__ unsigned            gIouCnt;
__device__ unsigned long long  gBestGt[BIMG * GGT];      // packed (iou_bits<<32)|(65535-a)
__device__ float               gNegBce[BIMG * AANC];     // 4MB

// ---------------- helpers ----------------
__device__ __forceinline__ float sl1(float d) {
    return d < 1.0f ? 0.5f * d * d : d - 0.5f;
}

__device__ __forceinline__ float loc_loss4(float4 P, float4 M) {
    float dcx = fabsf((P.x + P.z) * 0.5f - (M.x + M.z) * 0.5f);
    float dcy = fabsf((P.y + P.w) * 0.5f - (M.y + M.w) * 0.5f);
    float dw  = fabsf((P.z - P.x) - (M.z - M.x));
    float dh  = fabsf((P.w - P.y) - (M.w - M.y));
    return sl1(dcx) + sl1(dcy) + sl1(dw) + sl1(dh);
}

// ---------------- K0: reset accumulators ----------------
__global__ void k0_reset() {
    int i = threadIdx.x;
    if (i < BIMG) {
        gNumPos[i] = 0u; gLocSum[i] = 0.0; gPosBce[i] = 0.0;
        gNegSum[i] = 0.0; gPredCnt[i] = 0u;
    }
    if (i == BIMG) { gIouSum = 0.0; gIouCnt = 0u; }
    if (i < BIMG * GGT) gBestGt[i] = 65535ULL;   // iou=0, anchor idx 0
}

// ---------------- K1: main IoU + per-anchor pass ----------------
__global__ void __launch_bounds__(256) k1_main(
    const float4* __restrict__ bbox,      // [B,A] float4
    const float*  __restrict__ conf,      // [B,A]
    const float4* __restrict__ anchors,   // [A] float4
    const float4* __restrict__ gt)        // [B,G] float4
{
    __shared__ float4 sGt[GGT];
    __shared__ float  sAreaG[GGT];
    __shared__ unsigned long long sBest[GGT];

    const int b = blockIdx.y;
    const int a = blockIdx.x * 256 + threadIdx.x;
    const int t = threadIdx.x;
    const int lane = t & 31;

    if (t < GGT) {
        float4 g = gt[b * GGT + t];
        sGt[t] = g;
        sAreaG[t] = (g.z - g.x) * (g.w - g.y);
        sBest[t] = 65535ULL;
    }
    __syncthreads();

    const float4 an = anchors[a];
    const float areaA = (an.z - an.x) * (an.w - an.y);

    float bestv = -1.0f;
    int   besti = 0;

    #pragma unroll 8
    for (int g = 0; g < GGT; ++g) {
        float4 G = sGt[g];
        float ltx = fmaxf(an.x, G.x);
        float lty = fmaxf(an.y, G.y);
        float rbx = fminf(an.z, G.z);
        float rby = fminf(an.w, G.w);
        float w = fmaxf(rbx - ltx, 0.0f);
        float h = fmaxf(rby - lty, 0.0f);
        float inter = w * h;
        float uni = areaA + sAreaG[g] - inter;
        float iou = inter / (uni + 1e-6f);
        if (iou > bestv) { bestv = iou; besti = g; }
        unsigned ib = __float_as_uint(iou);
        // pre-filtered per-gt best-anchor update (stale read only causes an extra atomic)
        if ((unsigned)(sBest[g] >> 32) < ib) {
            atomicMax(&sBest[g],
                      ((unsigned long long)ib << 32) | (unsigned long long)(65535u - (unsigned)a));
        }
    }

    const float p = conf[b * AANC + a];
    const bool pos0 = bestv > 0.5f;

    // t=0 BCE (clamped at 100 like torch -100 log clamp)
    float bceNeg = fminf(-log1pf(-p), 100.0f);
    gNegBce[b * AANC + a] = pos0 ? 0.0f : bceNeg;

    unsigned mPred = __ballot_sync(0xffffffffu, p > 0.5f);
    unsigned mPos  = __ballot_sync(0xffffffffu, pos0);
    if (lane == 0) {
        if (mPred) atomicAdd(&gPredCnt[b], (unsigned)__popc(mPred));
        if (mPos)  atomicAdd(&gNumPos[b],  (unsigned)__popc(mPos));
    }

    if (pos0) {
        float4 M = sGt[besti];
        float4 P = bbox[b * AANC + a];
        float loc = loc_loss4(P, M);
        atomicAdd(&gLocSum[b], (double)loc);
        atomicAdd(&gPosBce[b], (double)fminf(-logf(p), 100.0f));
    }

    if (b == BIMG - 1) {
        float v = bestv > 0.0f ? bestv : 0.0f;
        #pragma unroll
        for (int o = 16; o; o >>= 1) v += __shfl_down_sync(0xffffffffu, v, o);
        unsigned mI = __ballot_sync(0xffffffffu, bestv > 0.0f);
        if (lane == 0) {
            if (v != 0.0f) atomicAdd(&gIouSum, (double)v);
            if (mI) atomicAdd(&gIouCnt, (unsigned)__popc(mI));
        }
    }

    __syncthreads();
    if (t < GGT) atomicMax(&gBestGt[b * GGT + t], sBest[t]);
}

// ---------------- K3: scatter (best-anchor-per-gt) fixup ----------------
__global__ void k3_fixup(
    const float4* __restrict__ bbox,
    const float*  __restrict__ conf,
    const float4* __restrict__ anchors,
    const float4* __restrict__ gt)
{
    const int b = blockIdx.x;      // 16 blocks
    const int g = threadIdx.x;     // 32 threads
    __shared__ int sIdx[GGT];

    unsigned long long pk = gBestGt[b * GGT + g];
    int a = 65535 - (int)(pk & 0xffffffffu);
    sIdx[g] = a;
    __syncwarp();

    // dedupe: lowest g owns the anchor
    bool owner = true;
    for (int j = 0; j < g; ++j)
        if (sIdx[j] == a) owner = false;
    if (!owner) return;

    // recompute this anchor's best-over-gt iou + matched gt
    float4 an = anchors[a];
    float areaA = (an.z - an.x) * (an.w - an.y);
    float bestv = -1.0f;
    float4 Mb = gt[b * GGT];
    for (int j = 0; j < GGT; ++j) {
        float4 G = gt[b * GGT + j];
        float ltx = fmaxf(an.x, G.x);
        float lty = fmaxf(an.y, G.y);
        float rbx = fminf(an.z, G.z);
        float rby = fminf(an.w, G.w);
        float w = fmaxf(rbx - ltx, 0.0f);
        float h = fmaxf(rby - lty, 0.0f);
        float inter = w * h;
        float areaG = (G.z - G.x) * (G.w - G.y);
        float uni = areaA + areaG - inter;
        float iou = inter / (uni + 1e-6f);
        if (iou > bestv) { bestv = iou; Mb = G; }
    }
    if (bestv > 0.5f) return;   // already counted as positive in K1

    float p = conf[b * AANC + a];
    atomicAdd(&gNumPos[b], 1u);
    atomicAdd(&gPosBce[b], (double)fminf(-logf(p), 100.0f));
    float4 P = bbox[b * AANC + a];
    atomicAdd(&gLocSum[b], (double)loc_loss4(P, Mb));
    gNegBce[b * AANC + a] = 0.0f;    // remove from negative pool
}

// ---------------- K4: per-image exact top-k sum via 8-bit radix select ----------------
__global__ void __launch_bounds__(512) k4_topk() {
    const int b = blockIdx.x;       // 16 blocks
    const int t = threadIdx.x;      // 512 threads
    __shared__ unsigned cnt[256];
    __shared__ unsigned sPrefix, sRemaining;
    __shared__ double   wsum[16];

    unsigned np = gNumPos[b];
    unsigned k = min(3u * np, (unsigned)AANC - np);
    if (t == 0) { sPrefix = 0u; sRemaining = k; }

    const float* __restrict__ nb = &gNegBce[b * AANC];

    for (int shift = 24; shift >= 0; shift -= 8) {
        if (t < 256) cnt[t] = 0u;
        if (t >= 256 && t < 512) cnt[t - 256] = 0u; // (covered twice-safe: both halves init)
        __syncthreads();
        // re-zero properly (512 threads, 256 bins): the above double-writes 0, fine.
        unsigned pref = sPrefix;
        for (int i = t; i < AANC; i += 512) {
            unsigned u = __float_as_uint(nb[i]);
            bool cand = (shift == 24) || ((u >> (shift + 8)) == pref);
            unsigned active = __ballot_sync(0xffffffffu, cand);
            if (cand) {
                unsigned bin = (u >> shift) & 255u;
                unsigned peers = __match_any_sync(active, bin);
                int leader = __ffs(peers) - 1;
                if ((t & 31) == leader) atomicAdd(&cnt[bin], (unsigned)__popc(peers));
            }
        }
        __syncthreads();
        if (t == 0) {
            unsigned rem = sRemaining;
            unsigned pr  = sPrefix;
            for (int bin = 255; bin >= 0; --bin) {
                unsigned c = cnt[bin];
                if (rem > c) { rem -= c; }
                else { pr = (pr << 8) | (unsigned)bin; break; }
            }
            sRemaining = rem; sPrefix = pr;
        }
        __syncthreads();
    }

    const unsigned vs = sPrefix;                 // bits of k-th largest value
    double sum = 0.0;
    for (int i = t; i < AANC; i += 512) {
        float v = nb[i];
        if (__float_as_uint(v) > vs) sum += (double)v;
    }
    #pragma unroll
    for (int o = 16; o; o >>= 1) sum += __shfl_down_sync(0xffffffffu, sum, o);
    if ((t & 31) == 0) wsum[t >> 5] = sum;
    __syncthreads();
    if (t == 0) {
        double s = 0.0;
        for (int w = 0; w < 16; ++w) s += wsum[w];
        gNegSum[b] = s + (double)sRemaining * (double)__uint_as_float(vs);
    }
}

// ---------------- K5: finalize ----------------
__global__ void k5_final(float* __restrict__ out) {
    unsigned npTot = 0;
    double loc = 0.0, confl = 0.0, cpen = 0.0;
    for (int b = 0; b < BIMG; ++b) {
        npTot += gNumPos[b];
        loc   += gLocSum[b];
        confl += gNegSum[b] + gPosBce[b];
        float diff = fabsf((float)((int)gPredCnt[b] - GGT));
        float pen = (diff <= 3.0f) ? diff * 0.2f
                                   : 0.6f + 0.2f * logf(fmaxf(diff - 2.0f, 1.0f));
        cpen += (double)pen;
    }
    float npos = (float)(npTot > 0u ? npTot : 1u);
    float tl = (float)loc / npos;
    float tc = (float)confl / npos;
    float tcnt = (float)(cpen) / (float)BIMG;
    float mean = (gIouCnt > 0u) ? (float)(gIouSum / (double)gIouCnt) : 0.1f;
    float iq = fminf(fmaxf(1.0f - mean, 0.1f), 0.9f);
    float total = (1.0f + iq) * tl + 1.0f * tc + 0.2f * tcnt;
    out[0] = total;
    out[1] = tc;
    out[2] = tl;
    out[3] = tcnt;
    out[4] = mean;
}

// ---------------- launch ----------------
extern "C" void kernel_launch(void* const* d_in, const int* in_sizes, int n_in,
                              void* d_out, int out_size) {
    const float4* bbox    = (const float4*)d_in[0];   // [16,65536,4]
    const float*  conf    = (const float*)d_in[1];    // [16,65536]
    const float4* anchors = (const float4*)d_in[2];   // [65536,4]
    const float4* gt      = (const float4*)d_in[3];   // [16,32,4]
    float* out = (float*)d_out;

    k0_reset<<<1, 512>>>();
    k1_main<<<dim3(AANC / 256, BIMG), 256>>>(bbox, conf, anchors, gt);
    k3_fixup<<<BIMG, GGT>>>(bbox, conf, anchors, gt);
    k4_topk<<<BIMG, 512>>>();
    k5_final<<<1, 1>>>(out);
}